// round 14
// baseline (speedup 1.0000x reference)
#include <cuda_runtime.h>
#include <math.h>

// out[b,c,:] = irfft( rfft(x,16384) * Kspec[c], 16384 )[:8192]
// Single kernel, NT=512, radix-16 Stockham (fwd [16,16,16,(2)], inv [(2),16,16,16]).
// Rows 0..255 (batch 0) are PRODUCERS: compute Kspec for their channel first
// (smooth/squash -> fwd FFT -> unpack -> store, flag release), then run their
// own conv row. Rows >= 256 spin on the channel flag just before the seam.
// Flags persist across graph replays (producers rewrite identical values).

#define N_FFT   8192
#define HALF_N  4096
#define NTC     512
#define L_SEQ   8192
#define NCHAN   256
#define NROWS   2048

#define SKM(a,M) ((a) + (M) * ((a) >> 4))
#define CB0     9728          // b0: also written with M=3 in inv s=2
#define CB1     8704          // b1: M=1 only
#define TWT16   512
#define TWH_N   2052

__device__ float2 g_kspec[(size_t)NCHAN * (N_FFT + 1)];
__device__ int    g_flag[NCHAN];   // zero-init; stays set after run 1 (benign)

__device__ __forceinline__ float2 cmul(float2 a, float2 b) {
    return make_float2(a.x * b.x - a.y * b.y, a.x * b.y + a.y * b.x);
}
__device__ __forceinline__ float2 cmulc(float2 a, float2 b) {   // a * conj(b)
    return make_float2(a.x * b.x + a.y * b.y, a.y * b.x - a.x * b.y);
}
__device__ __forceinline__ float2 cadd(float2 a, float2 b) { return make_float2(a.x + b.x, a.y + b.y); }
__device__ __forceinline__ float2 csub(float2 a, float2 b) { return make_float2(a.x - b.x, a.y - b.y); }

template <int INV>
__device__ __forceinline__ void dft8(float2* v) {
    const float u = 0.70710678118654752f;
    float2 apc = cadd(v[0], v[4]), amc = csub(v[0], v[4]);
    float2 bpd = cadd(v[2], v[6]), bmd = csub(v[2], v[6]);
    float2 E0 = cadd(apc, bpd), E2 = csub(apc, bpd), E1, E3;
    if (!INV) { E1 = make_float2(amc.x + bmd.y, amc.y - bmd.x); E3 = make_float2(amc.x - bmd.y, amc.y + bmd.x); }
    else      { E1 = make_float2(amc.x - bmd.y, amc.y + bmd.x); E3 = make_float2(amc.x + bmd.y, amc.y - bmd.x); }
    apc = cadd(v[1], v[5]); amc = csub(v[1], v[5]);
    bpd = cadd(v[3], v[7]); bmd = csub(v[3], v[7]);
    float2 O0 = cadd(apc, bpd), O2 = csub(apc, bpd), O1, O3;
    if (!INV) { O1 = make_float2(amc.x + bmd.y, amc.y - bmd.x); O3 = make_float2(amc.x - bmd.y, amc.y + bmd.x); }
    else      { O1 = make_float2(amc.x - bmd.y, amc.y + bmd.x); O3 = make_float2(amc.x + bmd.y, amc.y - bmd.x); }
    float2 T1, T2, T3;
    if (!INV) {
        T1 = make_float2(u * (O1.x + O1.y), u * (O1.y - O1.x));
        T2 = make_float2(O2.y, -O2.x);
        T3 = make_float2(u * (O3.y - O3.x), -u * (O3.x + O3.y));
    } else {
        T1 = make_float2(u * (O1.x - O1.y), u * (O1.x + O1.y));
        T2 = make_float2(-O2.y, O2.x);
        T3 = make_float2(-u * (O3.x + O3.y), u * (O3.x - O3.y));
    }
    v[0] = cadd(E0, O0); v[4] = csub(E0, O0);
    v[1] = cadd(E1, T1); v[5] = csub(E1, T1);
    v[2] = cadd(E2, T2); v[6] = csub(E2, T2);
    v[3] = cadd(E3, T3); v[7] = csub(E3, T3);
}

// forward dft8 with v[4..7] == 0 implied
__device__ __forceinline__ void dft8_half(float2* v) {
    const float u = 0.70710678118654752f;
    float2 E0 = cadd(v[0], v[2]), E2 = csub(v[0], v[2]);
    float2 E1 = make_float2(v[0].x + v[2].y, v[0].y - v[2].x);
    float2 E3 = make_float2(v[0].x - v[2].y, v[0].y + v[2].x);
    float2 O0 = cadd(v[1], v[3]), O2 = csub(v[1], v[3]);
    float2 O1 = make_float2(v[1].x + v[3].y, v[1].y - v[3].x);
    float2 O3 = make_float2(v[1].x - v[3].y, v[1].y + v[3].x);
    float2 T1 = make_float2(u * (O1.x + O1.y), u * (O1.y - O1.x));
    float2 T2 = make_float2(O2.y, -O2.x);
    float2 T3 = make_float2(u * (O3.y - O3.x), -u * (O3.x + O3.y));
    v[0] = cadd(E0, O0); v[4] = csub(E0, O0);
    v[1] = cadd(E1, T1); v[5] = csub(E1, T1);
    v[2] = cadd(E2, T2); v[6] = csub(E2, T2);
    v[3] = cadd(E3, T3); v[7] = csub(E3, T3);
}

template <int INV>
__device__ __forceinline__ void dft16_combine(float2* v, const float2* e8, const float2* o8) {
    const float c1 = 0.92387953251128674f, s1 = 0.38268343236508977f;
    const float uu = 0.70710678118654752f;
    const float sg = INV ? 1.0f : -1.0f;
    float2 t;
    v[0] = cadd(e8[0], o8[0]);                       v[8]  = csub(e8[0], o8[0]);
    t = cmul(o8[1], make_float2(c1, sg * s1));  v[1] = cadd(e8[1], t); v[9]  = csub(e8[1], t);
    t = cmul(o8[2], make_float2(uu, sg * uu));  v[2] = cadd(e8[2], t); v[10] = csub(e8[2], t);
    t = cmul(o8[3], make_float2(s1, sg * c1));  v[3] = cadd(e8[3], t); v[11] = csub(e8[3], t);
    t = make_float2(-sg * o8[4].y, sg * o8[4].x);
    v[4] = cadd(e8[4], t); v[12] = csub(e8[4], t);
    t = cmul(o8[5], make_float2(-s1, sg * c1)); v[5] = cadd(e8[5], t); v[13] = csub(e8[5], t);
    t = cmul(o8[6], make_float2(-uu, sg * uu)); v[6] = cadd(e8[6], t); v[14] = csub(e8[6], t);
    t = cmul(o8[7], make_float2(-c1, sg * s1)); v[7] = cadd(e8[7], t); v[15] = csub(e8[7], t);
}

template <int INV>
__device__ __forceinline__ void dft16(float2* v) {
    float2 e8[8], o8[8];
#pragma unroll
    for (int j = 0; j < 8; j++) { e8[j] = v[2 * j]; o8[j] = v[2 * j + 1]; }
    dft8<INV>(e8); dft8<INV>(o8);
    dft16_combine<INV>(v, e8, o8);
}

__device__ __forceinline__ void dft16_half(float2* v) {
    float2 e8[8], o8[8];
    e8[0] = v[0]; e8[1] = v[2]; e8[2] = v[4]; e8[3] = v[6];
    o8[0] = v[1]; o8[1] = v[3]; o8[2] = v[5]; o8[3] = v[7];
    dft8_half(e8); dft8_half(o8);
    dft16_combine<0>(v, e8, o8);
}

template <int INV, int RM, int WM, int S>
__device__ __forceinline__ void stage_r16(const float2* __restrict__ x, float2* __restrict__ y,
                                          const float2* __restrict__ tws, int tid) {
    const int q = tid & (S - 1);
    const int e = tid - q;
    float2 v[16];
#pragma unroll
    for (int j = 0; j < 16; j++) v[j] = x[SKM(tid + (j << 9), RM)];
    dft16<INV>(v);
    const int o = q + (e << 4);
    y[SKM(o, WM)] = v[0];
#pragma unroll
    for (int m = 1; m < 16; m++) {
        float2 w = tws[((m - 1) << 9) + e];
        y[SKM(o + m * S, WM)] = INV ? cmulc(v[m], w) : cmul(w, v[m]);
    }
}

// stage-1 (s=1, e=tid) write of a 16-wide register butterfly
__device__ __forceinline__ void stage1_write16(float2* __restrict__ y, const float2* v,
                                               const float2* __restrict__ tws, int tid) {
    const int o = tid << 4;
    y[SKM(o, 1)] = v[0];
#pragma unroll
    for (int m = 1; m < 16; m++)
        y[SKM(o + m, 1)] = cmul(tws[((m - 1) << 9) + tid], v[m]);
}

__device__ __forceinline__ void unpack_pair(float2 Zk, float2 Zn, float2 E,
                                            float2* Xk, float2* Xn) {
    float2 A = make_float2(0.5f * (Zk.x + Zn.x), 0.5f * (Zk.y - Zn.y));
    float2 D = make_float2(0.5f * (Zk.x - Zn.x), 0.5f * (Zk.y + Zn.y));
    float2 B = make_float2(D.y, -D.x);
    float2 EB = cmul(E, B);
    *Xk = make_float2(A.x + EB.x, A.y + EB.y);
    *Xn = make_float2(A.x - EB.x, -(A.y - EB.y));
}

__device__ __forceinline__ void spec_pair(float2 Zk, float2 Zn, float2 Kk, float2 Kn,
                                          float2 E, float2* Wk, float2* Wn) {
    float2 Xk, Xn;
    unpack_pair(Zk, Zn, E, &Xk, &Xn);
    float2 Yk = cmul(Xk, Kk);
    float2 Yn = cmul(Xn, Kn);
    float2 Ay = make_float2(0.5f * (Yk.x + Yn.x), 0.5f * (Yk.y - Yn.y));
    float2 Dy = make_float2(0.5f * (Yk.x - Yn.x), 0.5f * (Yk.y + Yn.y));
    float2 By = cmulc(Dy, E);
    *Wk = make_float2(Ay.x - By.y,  Ay.y + By.x);
    *Wn = make_float2(Ay.x + By.y, -Ay.y + By.x);
}

__device__ __forceinline__ float smooth_squash(const float* rk, int i) {
    float ssum = 0.f;
#pragma unroll
    for (int d = -3; d <= 3; d++) {
        int j = i + d;
        j = (j < 0) ? -j : j;
        j = (j > L_SEQ - 1) ? (2 * (L_SEQ - 1) - j) : j;
        ssum += rk[j];
    }
    float v = ssum * (1.0f / 7.0f);
    float a = fabsf(v) - 0.003f;
    return (a > 0.f) ? copysignf(a, v) : 0.f;
}

// smem: b0[CB0] | b1[CB1] | tws[15*512] | twh[2052]
#define SMEM_C ((CB0 + CB1 + 15 * TWT16 + TWH_N) * (int)sizeof(float2))

// ---------------------------------------------------------------------------
__global__ void __launch_bounds__(NTC, 1) fused_kernel(const float* __restrict__ x,
                                                       const float* __restrict__ kern,
                                                       float* __restrict__ out) {
    extern __shared__ float2 sm2[];
    float2* b0  = sm2;
    float2* b1  = sm2 + CB0;
    float2* tws = b1 + CB1;
    float2* twh = tws + 15 * TWT16;

    const int row = blockIdx.x;
    const int c   = row & (NCHAN - 1);
    const int tid = threadIdx.x;
    const bool producer = (row < NCHAN);
    const float2* xr = (const float2*)(x + (size_t)row * L_SEQ);

    float2 v1[8];
    if (producer) {
        // producers: stage kernel row into smem first (overlaps table fill)
        const float* kr = kern + (size_t)row * L_SEQ;
        float* rk = (float*)b1;
        for (int i = tid; i < L_SEQ; i += NTC) rk[i] = kr[i];
    } else {
        // consumers: issue x loads first (latency overlaps table fill)
#pragma unroll
        for (int j = 0; j < 8; j++) v1[j] = xr[tid + (j << 9)];
    }

    {   // fill twiddle tables
        float s, cc;
#pragma unroll
        for (int m = 1; m <= 15; m++) {
            sincospif((float)(m * tid) * (1.0f / 4096.0f), &s, &cc);
            tws[((m - 1) << 9) + tid] = make_float2(cc, -s);
        }
#pragma unroll
        for (int k = tid; k < TWH_N; k += NTC) {
            sincospif((float)k * (1.0f / 8192.0f), &s, &cc);
            twh[k] = make_float2(cc, -s);
        }
    }
    __syncthreads();

    // ======================= producer: kspec for channel c ==================
    if (producer) {
        const float* rk = (const float*)b1;
        {   // fused stage 1 from smooth/squash registers -> b0
            float2 v[16];
#pragma unroll
            for (int j = 0; j < 8; j++) {
                const int n = tid + (j << 9);
                v[j] = make_float2(smooth_squash(rk, 2 * n), smooth_squash(rk, 2 * n + 1));
            }
            dft16_half(v);
            stage1_write16(b0, v, tws, tid);
        }
        __syncthreads();                       // also: all rk (b1) reads done
        stage_r16<0,1,1,16>(b0, b1, tws, tid);  __syncthreads();
        stage_r16<0,1,1,256>(b1, b0, tws, tid); __syncthreads();
        // P = b0; fused r2 finisher + unpack + store (scaled 1/N)
        float2* Kc = g_kspec + (size_t)c * (N_FFT + 1);
        const float inv = 1.0f / (float)N_FFT;
#pragma unroll 1
        for (int u = 0; u < 4; u++) {
            const int q = tid + (u << 9);
            if (q == 0) {
                float2 Pa = b0[SKM(0,1)],    Pb = b0[SKM(4096,1)];
                float2 Pc = b0[SKM(2048,1)], Pd = b0[SKM(6144,1)];
                float2 Z0 = cadd(Pa, Pb), Z4 = csub(Pa, Pb);
                float2 Z2 = cadd(Pc, Pd), Z6 = csub(Pc, Pd);
                Kc[0]     = make_float2((Z0.x + Z0.y) * inv, 0.f);
                Kc[N_FFT] = make_float2((Z0.x - Z0.y) * inv, 0.f);
                Kc[4096]  = make_float2(Z4.x * inv, -Z4.y * inv);
                float2 X2, X6;
                unpack_pair(Z2, Z6, twh[2048], &X2, &X6);
                Kc[2048] = make_float2(X2.x * inv, X2.y * inv);
                Kc[6144] = make_float2(X6.x * inv, X6.y * inv);
            } else {
                const int r = 4096 - q;
                float2 Pa = b0[SKM(q,1)], Pb = b0[SKM(q + 4096,1)];
                float2 Pc = b0[SKM(r,1)], Pd = b0[SKM(r + 4096,1)];
                float2 Zq = cadd(Pa, Pb), Zq4 = csub(Pa, Pb);
                float2 Zr = cadd(Pc, Pd), Znq = csub(Pc, Pd);
                float2 Eq = twh[q];
                float2 Er = make_float2(-Eq.y, -Eq.x);
                float2 Xq, Xnq, Xr, Xpq;
                unpack_pair(Zq, Znq, Eq, &Xq, &Xnq);
                unpack_pair(Zr, Zq4, Er, &Xr, &Xpq);
                Kc[q]         = make_float2(Xq.x * inv,  Xq.y * inv);
                Kc[N_FFT - q] = make_float2(Xnq.x * inv, Xnq.y * inv);
                Kc[r]         = make_float2(Xr.x * inv,  Xr.y * inv);
                Kc[4096 + q]  = make_float2(Xpq.x * inv, Xpq.y * inv);
            }
        }
        __threadfence();
        __syncthreads();                       // all stores + seam reads done
        if (tid == 0) *((volatile int*)&g_flag[c]) = 1;
        // now load this row's x for the conv phase
#pragma unroll
        for (int j = 0; j < 8; j++) v1[j] = xr[tid + (j << 9)];
    }

    // ============================ conv phase ================================
    {   // fwd stage 1 (s=1, radix-16, upper half zero) -> b0
        float2 v[16];
#pragma unroll
        for (int j = 0; j < 8; j++) v[j] = v1[j];
        dft16_half(v);
        stage1_write16(b0, v, tws, tid);
    }
    __syncthreads();
    stage_r16<0,1,1,16>(b0, b1, tws, tid);  __syncthreads();
    stage_r16<0,1,1,256>(b1, b0, tws, tid); __syncthreads();
    // P = b0

    // acquire spectrum (no-op on producers; flags pre-set on replays)
    if (!producer) {
        if (tid == 0) {
            while (*((volatile int*)&g_flag[c]) == 0) { }
        }
        __syncthreads();
        __threadfence();
    }

    // fused: fwd r2 finisher + spectral multiply + inv r2 opener -> b1
    const float2* Kc = g_kspec + (size_t)c * (N_FFT + 1);
#pragma unroll 1
    for (int u = 0; u < 4; u++) {
        const int q = tid + (u << 9);
        if (q == 0) {
            float2 Pa = b0[SKM(0,1)],    Pb = b0[SKM(4096,1)];
            float2 Pc = b0[SKM(2048,1)], Pd = b0[SKM(6144,1)];
            float2 Z0 = cadd(Pa, Pb), Z4 = csub(Pa, Pb);
            float2 Z2 = cadd(Pc, Pd), Z6 = csub(Pc, Pd);
            float X0 = Z0.x + Z0.y, XN = Z0.x - Z0.y;
            float2 K0 = Kc[0], KN = Kc[N_FFT];
            float2 Y0 = make_float2(X0 * K0.x, X0 * K0.y);
            float2 YN = make_float2(XN * KN.x, XN * KN.y);
            float2 Ay = make_float2(0.5f * (Y0.x + YN.x), 0.5f * (Y0.y - YN.y));
            float2 Dy = make_float2(0.5f * (Y0.x - YN.x), 0.5f * (Y0.y + YN.y));
            float2 W0 = make_float2(Ay.x - Dy.y, Ay.y + Dy.x);
            float2 W4, Wd;
            spec_pair(Z4, Z4, Kc[4096], Kc[4096], make_float2(0.f, -1.f), &W4, &Wd);
            float2 W2, W6;
            spec_pair(Z2, Z6, Kc[2048], Kc[6144], twh[2048], &W2, &W6);
            b1[SKM(0,1)] = cadd(W0, W4);
            b1[SKM(1,1)] = csub(W0, W4);
            b1[SKM(4096,1)] = cadd(W2, W6);
            float2 t = csub(W2, W6);                 // * winv(2048) = i
            b1[SKM(4097,1)] = make_float2(-t.y, t.x);
        } else {
            const int r = 4096 - q;
            float2 Pa = b0[SKM(q,1)], Pb = b0[SKM(q + 4096,1)];
            float2 Pc = b0[SKM(r,1)], Pd = b0[SKM(r + 4096,1)];
            float2 Zq = cadd(Pa, Pb), Zq4 = csub(Pa, Pb);
            float2 Zr = cadd(Pc, Pd), Znq = csub(Pc, Pd);
            float2 Eq = twh[q];
            float2 Er = make_float2(-Eq.y, -Eq.x);
            float2 Wq, Wnq, Wr, Wpq;
            spec_pair(Zq, Znq, Kc[q], Kc[N_FFT - q], Eq, &Wq, &Wnq);
            spec_pair(Zr, Zq4, Kc[r], Kc[4096 + q], Er, &Wr, &Wpq);
            float2 wq = cmul(Eq, Eq);                 // W^q
            float2 wr = make_float2(-wq.x, wq.y);     // Er^2 = -conj(Eq^2)
            b1[SKM(2 * q, 1)]     = cadd(Wq, Wpq);
            b1[SKM(2 * q + 1, 1)] = cmulc(csub(Wq, Wpq), wq);
            b1[SKM(2 * r, 1)]     = cadd(Wr, Wnq);
            b1[SKM(2 * r + 1, 1)] = cmulc(csub(Wr, Wnq), wr);
        }
    }
    __syncthreads();

    stage_r16<1,1,3,2>(b1, b0, tws, tid);   __syncthreads();  // write M=3: conflict-free
    stage_r16<1,3,1,32>(b0, b1, tws, tid);  __syncthreads();

    {   // final inverse stage s=512 (e=0, twiddle-free): store first half to gmem
        float2 v[16];
#pragma unroll
        for (int j = 0; j < 16; j++) v[j] = b1[SKM(tid + (j << 9), 1)];
        dft16<1>(v);
        float2* outr = (float2*)(out + (size_t)row * L_SEQ);
#pragma unroll
        for (int m = 0; m < 8; m++) outr[tid + (m << 9)] = v[m];
    }
}

// ---------------------------------------------------------------------------
extern "C" void kernel_launch(void* const* d_in, const int* in_sizes, int n_in,
                              void* d_out, int out_size) {
    const float* x;
    const float* kern;
    if (in_sizes[0] == NROWS * L_SEQ) {
        x    = (const float*)d_in[0];
        kern = (const float*)d_in[1];
    } else {
        x    = (const float*)d_in[1];
        kern = (const float*)d_in[0];
    }
    float* out = (float*)d_out;

    cudaFuncSetAttribute(fused_kernel, cudaFuncAttributeMaxDynamicSharedMemorySize, SMEM_C);
    fused_kernel<<<NROWS, NTC, SMEM_C>>>(x, kern, out);
}

// round 15
// speedup vs baseline: 1.0726x; 1.0726x over previous
#include <cuda_runtime.h>
#include <math.h>

// out[b,c,:] = irfft( rfft(x,16384) * Kspec[c], 16384 )[:8192]
// Two kernels, both NT=512 radix-16 Stockham:
//   kspec (256 CTAs): smooth/squash -> fwd FFT -> unpack -> g_kspec store,
//     then cudaTriggerProgrammaticLaunchCompletion().
//   conv (2048 CTAs, PDL-launched): fwd FFT, cudaGridDependencySynchronize(),
//     fused r2 seams + spectral multiply, inverse FFT, store.

#define N_FFT   8192
#define HALF_N  4096
#define NTC     512
#define L_SEQ   8192
#define NCHAN   256
#define NROWS   2048

#define SKM(a,M) ((a) + (M) * ((a) >> 4))
#define CB0     9728          // b0: also written with M=3 in inv s=2
#define CB1     8704          // b1: M=1 only
#define TWT16   512
#define TWH_N   2052

__device__ float2 g_kspec[(size_t)NCHAN * (N_FFT + 1)];

__device__ __forceinline__ float2 cmul(float2 a, float2 b) {
    return make_float2(a.x * b.x - a.y * b.y, a.x * b.y + a.y * b.x);
}
__device__ __forceinline__ float2 cmulc(float2 a, float2 b) {   // a * conj(b)
    return make_float2(a.x * b.x + a.y * b.y, a.y * b.x - a.x * b.y);
}
__device__ __forceinline__ float2 cadd(float2 a, float2 b) { return make_float2(a.x + b.x, a.y + b.y); }
__device__ __forceinline__ float2 csub(float2 a, float2 b) { return make_float2(a.x - b.x, a.y - b.y); }

template <int INV>
__device__ __forceinline__ void dft8(float2* v) {
    const float u = 0.70710678118654752f;
    float2 apc = cadd(v[0], v[4]), amc = csub(v[0], v[4]);
    float2 bpd = cadd(v[2], v[6]), bmd = csub(v[2], v[6]);
    float2 E0 = cadd(apc, bpd), E2 = csub(apc, bpd), E1, E3;
    if (!INV) { E1 = make_float2(amc.x + bmd.y, amc.y - bmd.x); E3 = make_float2(amc.x - bmd.y, amc.y + bmd.x); }
    else      { E1 = make_float2(amc.x - bmd.y, amc.y + bmd.x); E3 = make_float2(amc.x + bmd.y, amc.y - bmd.x); }
    apc = cadd(v[1], v[5]); amc = csub(v[1], v[5]);
    bpd = cadd(v[3], v[7]); bmd = csub(v[3], v[7]);
    float2 O0 = cadd(apc, bpd), O2 = csub(apc, bpd), O1, O3;
    if (!INV) { O1 = make_float2(amc.x + bmd.y, amc.y - bmd.x); O3 = make_float2(amc.x - bmd.y, amc.y + bmd.x); }
    else      { O1 = make_float2(amc.x - bmd.y, amc.y + bmd.x); O3 = make_float2(amc.x + bmd.y, amc.y - bmd.x); }
    float2 T1, T2, T3;
    if (!INV) {
        T1 = make_float2(u * (O1.x + O1.y), u * (O1.y - O1.x));
        T2 = make_float2(O2.y, -O2.x);
        T3 = make_float2(u * (O3.y - O3.x), -u * (O3.x + O3.y));
    } else {
        T1 = make_float2(u * (O1.x - O1.y), u * (O1.x + O1.y));
        T2 = make_float2(-O2.y, O2.x);
        T3 = make_float2(-u * (O3.x + O3.y), u * (O3.x - O3.y));
    }
    v[0] = cadd(E0, O0); v[4] = csub(E0, O0);
    v[1] = cadd(E1, T1); v[5] = csub(E1, T1);
    v[2] = cadd(E2, T2); v[6] = csub(E2, T2);
    v[3] = cadd(E3, T3); v[7] = csub(E3, T3);
}

__device__ __forceinline__ void dft8_half(float2* v) {
    const float u = 0.70710678118654752f;
    float2 E0 = cadd(v[0], v[2]), E2 = csub(v[0], v[2]);
    float2 E1 = make_float2(v[0].x + v[2].y, v[0].y - v[2].x);
    float2 E3 = make_float2(v[0].x - v[2].y, v[0].y + v[2].x);
    float2 O0 = cadd(v[1], v[3]), O2 = csub(v[1], v[3]);
    float2 O1 = make_float2(v[1].x + v[3].y, v[1].y - v[3].x);
    float2 O3 = make_float2(v[1].x - v[3].y, v[1].y + v[3].x);
    float2 T1 = make_float2(u * (O1.x + O1.y), u * (O1.y - O1.x));
    float2 T2 = make_float2(O2.y, -O2.x);
    float2 T3 = make_float2(u * (O3.y - O3.x), -u * (O3.x + O3.y));
    v[0] = cadd(E0, O0); v[4] = csub(E0, O0);
    v[1] = cadd(E1, T1); v[5] = csub(E1, T1);
    v[2] = cadd(E2, T2); v[6] = csub(E2, T2);
    v[3] = cadd(E3, T3); v[7] = csub(E3, T3);
}

template <int INV>
__device__ __forceinline__ void dft16_combine(float2* v, const float2* e8, const float2* o8) {
    const float c1 = 0.92387953251128674f, s1 = 0.38268343236508977f;
    const float uu = 0.70710678118654752f;
    const float sg = INV ? 1.0f : -1.0f;
    float2 t;
    v[0] = cadd(e8[0], o8[0]);                       v[8]  = csub(e8[0], o8[0]);
    t = cmul(o8[1], make_float2(c1, sg * s1));  v[1] = cadd(e8[1], t); v[9]  = csub(e8[1], t);
    t = cmul(o8[2], make_float2(uu, sg * uu));  v[2] = cadd(e8[2], t); v[10] = csub(e8[2], t);
    t = cmul(o8[3], make_float2(s1, sg * c1));  v[3] = cadd(e8[3], t); v[11] = csub(e8[3], t);
    t = make_float2(-sg * o8[4].y, sg * o8[4].x);
    v[4] = cadd(e8[4], t); v[12] = csub(e8[4], t);
    t = cmul(o8[5], make_float2(-s1, sg * c1)); v[5] = cadd(e8[5], t); v[13] = csub(e8[5], t);
    t = cmul(o8[6], make_float2(-uu, sg * uu)); v[6] = cadd(e8[6], t); v[14] = csub(e8[6], t);
    t = cmul(o8[7], make_float2(-c1, sg * s1)); v[7] = cadd(e8[7], t); v[15] = csub(e8[7], t);
}

template <int INV>
__device__ __forceinline__ void dft16(float2* v) {
    float2 e8[8], o8[8];
#pragma unroll
    for (int j = 0; j < 8; j++) { e8[j] = v[2 * j]; o8[j] = v[2 * j + 1]; }
    dft8<INV>(e8); dft8<INV>(o8);
    dft16_combine<INV>(v, e8, o8);
}

__device__ __forceinline__ void dft16_half(float2* v) {
    float2 e8[8], o8[8];
    e8[0] = v[0]; e8[1] = v[2]; e8[2] = v[4]; e8[3] = v[6];
    o8[0] = v[1]; o8[1] = v[3]; o8[2] = v[5]; o8[3] = v[7];
    dft8_half(e8); dft8_half(o8);
    dft16_combine<0>(v, e8, o8);
}

template <int INV, int RM, int WM, int S>
__device__ __forceinline__ void stage_r16(const float2* __restrict__ x, float2* __restrict__ y,
                                          const float2* __restrict__ tws, int tid) {
    const int q = tid & (S - 1);
    const int e = tid - q;
    float2 v[16];
#pragma unroll
    for (int j = 0; j < 16; j++) v[j] = x[SKM(tid + (j << 9), RM)];
    dft16<INV>(v);
    const int o = q + (e << 4);
    y[SKM(o, WM)] = v[0];
#pragma unroll
    for (int m = 1; m < 16; m++) {
        float2 w = tws[((m - 1) << 9) + e];
        y[SKM(o + m * S, WM)] = INV ? cmulc(v[m], w) : cmul(w, v[m]);
    }
}

__device__ __forceinline__ void stage1_write16(float2* __restrict__ y, const float2* v,
                                               const float2* __restrict__ tws, int tid) {
    const int o = tid << 4;
    y[SKM(o, 1)] = v[0];
#pragma unroll
    for (int m = 1; m < 16; m++)
        y[SKM(o + m, 1)] = cmul(tws[((m - 1) << 9) + tid], v[m]);
}

__device__ __forceinline__ void fill_tw(float2* tws, float2* twh, int tid) {
    float s, cc;
#pragma unroll
    for (int m = 1; m <= 15; m++) {
        sincospif((float)(m * tid) * (1.0f / 4096.0f), &s, &cc);
        tws[((m - 1) << 9) + tid] = make_float2(cc, -s);
    }
#pragma unroll
    for (int k = tid; k < TWH_N; k += NTC) {
        sincospif((float)k * (1.0f / 8192.0f), &s, &cc);
        twh[k] = make_float2(cc, -s);
    }
}

__device__ __forceinline__ void unpack_pair(float2 Zk, float2 Zn, float2 E,
                                            float2* Xk, float2* Xn) {
    float2 A = make_float2(0.5f * (Zk.x + Zn.x), 0.5f * (Zk.y - Zn.y));
    float2 D = make_float2(0.5f * (Zk.x - Zn.x), 0.5f * (Zk.y + Zn.y));
    float2 B = make_float2(D.y, -D.x);
    float2 EB = cmul(E, B);
    *Xk = make_float2(A.x + EB.x, A.y + EB.y);
    *Xn = make_float2(A.x - EB.x, -(A.y - EB.y));
}

__device__ __forceinline__ void spec_pair(float2 Zk, float2 Zn, float2 Kk, float2 Kn,
                                          float2 E, float2* Wk, float2* Wn) {
    float2 Xk, Xn;
    unpack_pair(Zk, Zn, E, &Xk, &Xn);
    float2 Yk = cmul(Xk, Kk);
    float2 Yn = cmul(Xn, Kn);
    float2 Ay = make_float2(0.5f * (Yk.x + Yn.x), 0.5f * (Yk.y - Yn.y));
    float2 Dy = make_float2(0.5f * (Yk.x - Yn.x), 0.5f * (Yk.y + Yn.y));
    float2 By = cmulc(Dy, E);
    *Wk = make_float2(Ay.x - By.y,  Ay.y + By.x);
    *Wn = make_float2(Ay.x + By.y, -Ay.y + By.x);
}

__device__ __forceinline__ float smooth_squash(const float* rk, int i) {
    float ssum = 0.f;
#pragma unroll
    for (int d = -3; d <= 3; d++) {
        int j = i + d;
        j = (j < 0) ? -j : j;
        j = (j > L_SEQ - 1) ? (2 * (L_SEQ - 1) - j) : j;
        ssum += rk[j];
    }
    float v = ssum * (1.0f / 7.0f);
    float a = fabsf(v) - 0.003f;
    return (a > 0.f) ? copysignf(a, v) : 0.f;
}

// smem: b0[CB0] | b1[CB1] | tws[15*512] | twh[2052]
#define SMEM_C ((CB0 + CB1 + 15 * TWT16 + TWH_N) * (int)sizeof(float2))

// ---------------------------------------------------------------------------
// kspec: radix-16 forward-only, one CTA per channel
// ---------------------------------------------------------------------------
__global__ void __launch_bounds__(NTC, 1) kspec_kernel(const float* __restrict__ kern) {
    extern __shared__ float2 sm2[];
    float2* b0  = sm2;
    float2* b1  = sm2 + CB0;
    float2* tws = b1 + CB1;
    float2* twh = tws + 15 * TWT16;
    float*  rk  = (float*)b1;

    const int c   = blockIdx.x;
    const int tid = threadIdx.x;
    const float* kr = kern + (size_t)c * L_SEQ;

    for (int i = tid; i < L_SEQ; i += NTC) rk[i] = kr[i];
    fill_tw(tws, twh, tid);
    __syncthreads();

    {   // fused stage 1 from smooth/squash registers -> b0
        float2 v[16];
#pragma unroll
        for (int j = 0; j < 8; j++) {
            const int n = tid + (j << 9);
            v[j] = make_float2(smooth_squash(rk, 2 * n), smooth_squash(rk, 2 * n + 1));
        }
        dft16_half(v);
        stage1_write16(b0, v, tws, tid);
    }
    __syncthreads();                            // also: rk (b1) fully consumed
    stage_r16<0,1,1,16>(b0, b1, tws, tid);  __syncthreads();
    stage_r16<0,1,1,256>(b1, b0, tws, tid); __syncthreads();
    // P = b0; fused r2 finisher + unpack + store (scaled 1/N)
    float2* Kc = g_kspec + (size_t)c * (N_FFT + 1);
    const float inv = 1.0f / (float)N_FFT;
#pragma unroll 1
    for (int u = 0; u < 4; u++) {
        const int q = tid + (u << 9);
        if (q == 0) {
            float2 Pa = b0[SKM(0,1)],    Pb = b0[SKM(4096,1)];
            float2 Pc = b0[SKM(2048,1)], Pd = b0[SKM(6144,1)];
            float2 Z0 = cadd(Pa, Pb), Z4 = csub(Pa, Pb);
            float2 Z2 = cadd(Pc, Pd), Z6 = csub(Pc, Pd);
            Kc[0]     = make_float2((Z0.x + Z0.y) * inv, 0.f);
            Kc[N_FFT] = make_float2((Z0.x - Z0.y) * inv, 0.f);
            Kc[4096]  = make_float2(Z4.x * inv, -Z4.y * inv);
            float2 X2, X6;
            unpack_pair(Z2, Z6, twh[2048], &X2, &X6);
            Kc[2048] = make_float2(X2.x * inv, X2.y * inv);
            Kc[6144] = make_float2(X6.x * inv, X6.y * inv);
        } else {
            const int r = 4096 - q;
            float2 Pa = b0[SKM(q,1)], Pb = b0[SKM(q + 4096,1)];
            float2 Pc = b0[SKM(r,1)], Pd = b0[SKM(r + 4096,1)];
            float2 Zq = cadd(Pa, Pb), Zq4 = csub(Pa, Pb);
            float2 Zr = cadd(Pc, Pd), Znq = csub(Pc, Pd);
            float2 Eq = twh[q];
            float2 Er = make_float2(-Eq.y, -Eq.x);        // E(4096-q)
            float2 Xq, Xnq, Xr, Xpq;
            unpack_pair(Zq, Znq, Eq, &Xq, &Xnq);
            unpack_pair(Zr, Zq4, Er, &Xr, &Xpq);
            Kc[q]         = make_float2(Xq.x * inv,  Xq.y * inv);
            Kc[N_FFT - q] = make_float2(Xnq.x * inv, Xnq.y * inv);
            Kc[r]         = make_float2(Xr.x * inv,  Xr.y * inv);
            Kc[4096 + q]  = make_float2(Xpq.x * inv, Xpq.y * inv);
        }
    }
#if __CUDA_ARCH__ >= 900
    cudaTriggerProgrammaticLaunchCompletion();
#endif
}

// ---------------------------------------------------------------------------
// conv: radix-16, PDL secondary. Fwd FFT is pre-dependency work; grid sync
// before reading g_kspec.
// ---------------------------------------------------------------------------
__global__ void __launch_bounds__(NTC, 1) conv_kernel(const float* __restrict__ x,
                                                      float* __restrict__ out) {
    extern __shared__ float2 sm2[];
    float2* b0  = sm2;
    float2* b1  = sm2 + CB0;
    float2* tws = b1 + CB1;
    float2* twh = tws + 15 * TWT16;

    const int row = blockIdx.x;
    const int c   = row & (NCHAN - 1);
    const int tid = threadIdx.x;
    const float2* xr = (const float2*)(x + (size_t)row * L_SEQ);

    // stage-1 global loads FIRST (latency overlaps the sincospif table fill)
    float2 v1[8];
#pragma unroll
    for (int j = 0; j < 8; j++) v1[j] = xr[tid + (j << 9)];

    fill_tw(tws, twh, tid);
    __syncthreads();

    {   // fwd stage 1 (s=1, radix-16, upper half zero) -> b0
        float2 v[16];
#pragma unroll
        for (int j = 0; j < 8; j++) v[j] = v1[j];
        dft16_half(v);
        stage1_write16(b0, v, tws, tid);
    }
    __syncthreads();
    stage_r16<0,1,1,16>(b0, b1, tws, tid);  __syncthreads();
    stage_r16<0,1,1,256>(b1, b0, tws, tid); __syncthreads();
    // P = b0

#if __CUDA_ARCH__ >= 900
    cudaGridDependencySynchronize();          // g_kspec ready past this point
#endif

    // fused: fwd r2 finisher + spectral multiply + inv r2 opener -> b1
    const float2* Kc = g_kspec + (size_t)c * (N_FFT + 1);
#pragma unroll 1
    for (int u = 0; u < 4; u++) {
        const int q = tid + (u << 9);
        if (q == 0) {
            float2 Pa = b0[SKM(0,1)],    Pb = b0[SKM(4096,1)];
            float2 Pc = b0[SKM(2048,1)], Pd = b0[SKM(6144,1)];
            float2 Z0 = cadd(Pa, Pb), Z4 = csub(Pa, Pb);
            float2 Z2 = cadd(Pc, Pd), Z6 = csub(Pc, Pd);
            float X0 = Z0.x + Z0.y, XN = Z0.x - Z0.y;
            float2 K0 = Kc[0], KN = Kc[N_FFT];
            float2 Y0 = make_float2(X0 * K0.x, X0 * K0.y);
            float2 YN = make_float2(XN * KN.x, XN * KN.y);
            float2 Ay = make_float2(0.5f * (Y0.x + YN.x), 0.5f * (Y0.y - YN.y));
            float2 Dy = make_float2(0.5f * (Y0.x - YN.x), 0.5f * (Y0.y + YN.y));
            float2 W0 = make_float2(Ay.x - Dy.y, Ay.y + Dy.x);
            float2 W4, Wd;
            spec_pair(Z4, Z4, Kc[4096], Kc[4096], make_float2(0.f, -1.f), &W4, &Wd);
            float2 W2, W6;
            spec_pair(Z2, Z6, Kc[2048], Kc[6144], twh[2048], &W2, &W6);
            b1[SKM(0,1)] = cadd(W0, W4);
            b1[SKM(1,1)] = csub(W0, W4);
            b1[SKM(4096,1)] = cadd(W2, W6);
            float2 t = csub(W2, W6);                 // * winv(2048) = i
            b1[SKM(4097,1)] = make_float2(-t.y, t.x);
        } else {
            const int r = 4096 - q;
            float2 Pa = b0[SKM(q,1)], Pb = b0[SKM(q + 4096,1)];
            float2 Pc = b0[SKM(r,1)], Pd = b0[SKM(r + 4096,1)];
            float2 Zq = cadd(Pa, Pb), Zq4 = csub(Pa, Pb);
            float2 Zr = cadd(Pc, Pd), Znq = csub(Pc, Pd);
            float2 Eq = twh[q];
            float2 Er = make_float2(-Eq.y, -Eq.x);
            float2 Wq, Wnq, Wr, Wpq;
            spec_pair(Zq, Znq, Kc[q], Kc[N_FFT - q], Eq, &Wq, &Wnq);
            spec_pair(Zr, Zq4, Kc[r], Kc[4096 + q], Er, &Wr, &Wpq);
            float2 wq = cmul(Eq, Eq);                 // W^q
            float2 wr = make_float2(-wq.x, wq.y);     // Er^2 = -conj(Eq^2)
            b1[SKM(2 * q, 1)]     = cadd(Wq, Wpq);
            b1[SKM(2 * q + 1, 1)] = cmulc(csub(Wq, Wpq), wq);
            b1[SKM(2 * r, 1)]     = cadd(Wr, Wnq);
            b1[SKM(2 * r + 1, 1)] = cmulc(csub(Wr, Wnq), wr);
        }
    }
    __syncthreads();

    stage_r16<1,1,3,2>(b1, b0, tws, tid);   __syncthreads();  // write M=3: conflict-free
    stage_r16<1,3,1,32>(b0, b1, tws, tid);  __syncthreads();

    {   // final inverse stage s=512 (e=0, twiddle-free): store first half to gmem
        float2 v[16];
#pragma unroll
        for (int j = 0; j < 16; j++) v[j] = b1[SKM(tid + (j << 9), 1)];
        dft16<1>(v);
        float2* outr = (float2*)(out + (size_t)row * L_SEQ);
#pragma unroll
        for (int m = 0; m < 8; m++) outr[tid + (m << 9)] = v[m];
    }
}

// ---------------------------------------------------------------------------
extern "C" void kernel_launch(void* const* d_in, const int* in_sizes, int n_in,
                              void* d_out, int out_size) {
    const float* x;
    const float* kern;
    if (in_sizes[0] == NROWS * L_SEQ) {
        x    = (const float*)d_in[0];
        kern = (const float*)d_in[1];
    } else {
        x    = (const float*)d_in[1];
        kern = (const float*)d_in[0];
    }
    float* out = (float*)d_out;

    cudaFuncSetAttribute(kspec_kernel, cudaFuncAttributeMaxDynamicSharedMemorySize, SMEM_C);
    cudaFuncSetAttribute(conv_kernel,  cudaFuncAttributeMaxDynamicSharedMemorySize, SMEM_C);

    kspec_kernel<<<NCHAN, NTC, SMEM_C>>>(kern);

    // conv as PDL secondary: may begin launching while kspec drains; the
    // in-kernel cudaGridDependencySynchronize() guards the g_kspec reads.
    cudaLaunchConfig_t cfg = {};
    cfg.gridDim = dim3(NROWS, 1, 1);
    cfg.blockDim = dim3(NTC, 1, 1);
    cfg.dynamicSmemBytes = SMEM_C;
    cfg.stream = 0;
    cudaLaunchAttribute attr[1];
    attr[0].id = cudaLaunchAttributeProgrammaticStreamSerialization;
    attr[0].val.programmaticStreamSerializationAllowed = 1;
    cfg.attrs = attr;
    cfg.numAttrs = 1;
    cudaLaunchKernelEx(&cfg, conv_kernel, x, out);
}

// round 16
// speedup vs baseline: 1.1171x; 1.0415x over previous
#include <cuda_runtime.h>
#include <math.h>

// out[b,c,:] = irfft( rfft(x,16384) * Kspec[c], 16384 )[:8192]
// kspec: radix-8 NT=1024 (R13/R11-proven), triggers PDL completion after stores.
// conv:  radix-16 NT=512 (R13-proven), PDL secondary; grid-sync after fwd FFT.

#define N_FFT   8192
#define HALF_N  4096
#define NTK     1024
#define NTC     512
#define L_SEQ   8192
#define NCHAN   256
#define NROWS   2048

#define SKM(a,M) ((a) + (M) * ((a) >> 4))
#define KBUF    9216
#define CB0     9728
#define CB1     8704
#define TWT8    1024
#define TWT16   512
#define TWH_N   2052

__device__ float2 g_kspec[(size_t)NCHAN * (N_FFT + 1)];

__device__ __forceinline__ float2 cmul(float2 a, float2 b) {
    return make_float2(a.x * b.x - a.y * b.y, a.x * b.y + a.y * b.x);
}
__device__ __forceinline__ float2 cmulc(float2 a, float2 b) {   // a * conj(b)
    return make_float2(a.x * b.x + a.y * b.y, a.y * b.x - a.x * b.y);
}
__device__ __forceinline__ float2 cadd(float2 a, float2 b) { return make_float2(a.x + b.x, a.y + b.y); }
__device__ __forceinline__ float2 csub(float2 a, float2 b) { return make_float2(a.x - b.x, a.y - b.y); }

template <int INV>
__device__ __forceinline__ void dft8(float2* v) {
    const float u = 0.70710678118654752f;
    float2 apc = cadd(v[0], v[4]), amc = csub(v[0], v[4]);
    float2 bpd = cadd(v[2], v[6]), bmd = csub(v[2], v[6]);
    float2 E0 = cadd(apc, bpd), E2 = csub(apc, bpd), E1, E3;
    if (!INV) { E1 = make_float2(amc.x + bmd.y, amc.y - bmd.x); E3 = make_float2(amc.x - bmd.y, amc.y + bmd.x); }
    else      { E1 = make_float2(amc.x - bmd.y, amc.y + bmd.x); E3 = make_float2(amc.x + bmd.y, amc.y - bmd.x); }
    apc = cadd(v[1], v[5]); amc = csub(v[1], v[5]);
    bpd = cadd(v[3], v[7]); bmd = csub(v[3], v[7]);
    float2 O0 = cadd(apc, bpd), O2 = csub(apc, bpd), O1, O3;
    if (!INV) { O1 = make_float2(amc.x + bmd.y, amc.y - bmd.x); O3 = make_float2(amc.x - bmd.y, amc.y + bmd.x); }
    else      { O1 = make_float2(amc.x - bmd.y, amc.y + bmd.x); O3 = make_float2(amc.x + bmd.y, amc.y - bmd.x); }
    float2 T1, T2, T3;
    if (!INV) {
        T1 = make_float2(u * (O1.x + O1.y), u * (O1.y - O1.x));
        T2 = make_float2(O2.y, -O2.x);
        T3 = make_float2(u * (O3.y - O3.x), -u * (O3.x + O3.y));
    } else {
        T1 = make_float2(u * (O1.x - O1.y), u * (O1.x + O1.y));
        T2 = make_float2(-O2.y, O2.x);
        T3 = make_float2(-u * (O3.x + O3.y), u * (O3.x - O3.y));
    }
    v[0] = cadd(E0, O0); v[4] = csub(E0, O0);
    v[1] = cadd(E1, T1); v[5] = csub(E1, T1);
    v[2] = cadd(E2, T2); v[6] = csub(E2, T2);
    v[3] = cadd(E3, T3); v[7] = csub(E3, T3);
}

__device__ __forceinline__ void dft8_half(float2* v) {
    const float u = 0.70710678118654752f;
    float2 E0 = cadd(v[0], v[2]), E2 = csub(v[0], v[2]);
    float2 E1 = make_float2(v[0].x + v[2].y, v[0].y - v[2].x);
    float2 E3 = make_float2(v[0].x - v[2].y, v[0].y + v[2].x);
    float2 O0 = cadd(v[1], v[3]), O2 = csub(v[1], v[3]);
    float2 O1 = make_float2(v[1].x + v[3].y, v[1].y - v[3].x);
    float2 O3 = make_float2(v[1].x - v[3].y, v[1].y + v[3].x);
    float2 T1 = make_float2(u * (O1.x + O1.y), u * (O1.y - O1.x));
    float2 T2 = make_float2(O2.y, -O2.x);
    float2 T3 = make_float2(u * (O3.y - O3.x), -u * (O3.x + O3.y));
    v[0] = cadd(E0, O0); v[4] = csub(E0, O0);
    v[1] = cadd(E1, T1); v[5] = csub(E1, T1);
    v[2] = cadd(E2, T2); v[6] = csub(E2, T2);
    v[3] = cadd(E3, T3); v[7] = csub(E3, T3);
}

template <int INV>
__device__ __forceinline__ void dft16_combine(float2* v, const float2* e8, const float2* o8) {
    const float c1 = 0.92387953251128674f, s1 = 0.38268343236508977f;
    const float uu = 0.70710678118654752f;
    const float sg = INV ? 1.0f : -1.0f;
    float2 t;
    v[0] = cadd(e8[0], o8[0]);                       v[8]  = csub(e8[0], o8[0]);
    t = cmul(o8[1], make_float2(c1, sg * s1));  v[1] = cadd(e8[1], t); v[9]  = csub(e8[1], t);
    t = cmul(o8[2], make_float2(uu, sg * uu));  v[2] = cadd(e8[2], t); v[10] = csub(e8[2], t);
    t = cmul(o8[3], make_float2(s1, sg * c1));  v[3] = cadd(e8[3], t); v[11] = csub(e8[3], t);
    t = make_float2(-sg * o8[4].y, sg * o8[4].x);
    v[4] = cadd(e8[4], t); v[12] = csub(e8[4], t);
    t = cmul(o8[5], make_float2(-s1, sg * c1)); v[5] = cadd(e8[5], t); v[13] = csub(e8[5], t);
    t = cmul(o8[6], make_float2(-uu, sg * uu)); v[6] = cadd(e8[6], t); v[14] = csub(e8[6], t);
    t = cmul(o8[7], make_float2(-c1, sg * s1)); v[7] = cadd(e8[7], t); v[15] = csub(e8[7], t);
}

template <int INV>
__device__ __forceinline__ void dft16(float2* v) {
    float2 e8[8], o8[8];
#pragma unroll
    for (int j = 0; j < 8; j++) { e8[j] = v[2 * j]; o8[j] = v[2 * j + 1]; }
    dft8<INV>(e8); dft8<INV>(o8);
    dft16_combine<INV>(v, e8, o8);
}

__device__ __forceinline__ void dft16_half(float2* v) {
    float2 e8[8], o8[8];
    e8[0] = v[0]; e8[1] = v[2]; e8[2] = v[4]; e8[3] = v[6];
    o8[0] = v[1]; o8[1] = v[3]; o8[2] = v[5]; o8[3] = v[7];
    dft8_half(e8); dft8_half(o8);
    dft16_combine<0>(v, e8, o8);
}

// radix-8 stage (kspec, NT=1024)
template <int INV, int RM, int WM>
__device__ __forceinline__ void stage_r8(const float2* __restrict__ x, float2* __restrict__ y,
                                         const float2* __restrict__ tws, int s, int tid) {
    const int q = tid & (s - 1);
    const int e = tid - q;
    float2 v[8];
#pragma unroll
    for (int j = 0; j < 8; j++) v[j] = x[SKM(tid + (j << 10), RM)];
    dft8<INV>(v);
    const int o = q + (e << 3);
    y[SKM(o, WM)] = v[0];
#pragma unroll
    for (int m = 1; m < 8; m++) {
        float2 w = tws[((m - 1) << 10) + e];
        y[SKM(o + m * s, WM)] = INV ? cmulc(v[m], w) : cmul(w, v[m]);
    }
}

// radix-16 stage (conv, NT=512)
template <int INV, int RM, int WM, int S>
__device__ __forceinline__ void stage_r16(const float2* __restrict__ x, float2* __restrict__ y,
                                          const float2* __restrict__ tws, int tid) {
    const int q = tid & (S - 1);
    const int e = tid - q;
    float2 v[16];
#pragma unroll
    for (int j = 0; j < 16; j++) v[j] = x[SKM(tid + (j << 9), RM)];
    dft16<INV>(v);
    const int o = q + (e << 4);
    y[SKM(o, WM)] = v[0];
#pragma unroll
    for (int m = 1; m < 16; m++) {
        float2 w = tws[((m - 1) << 9) + e];
        y[SKM(o + m * S, WM)] = INV ? cmulc(v[m], w) : cmul(w, v[m]);
    }
}

__device__ __forceinline__ void stage1_write16(float2* __restrict__ y, const float2* v,
                                               const float2* __restrict__ tws, int tid) {
    const int o = tid << 4;
    y[SKM(o, 1)] = v[0];
#pragma unroll
    for (int m = 1; m < 16; m++)
        y[SKM(o + m, 1)] = cmul(tws[((m - 1) << 9) + tid], v[m]);
}

__device__ __forceinline__ void unpack_pair(float2 Zk, float2 Zn, float2 E,
                                            float2* Xk, float2* Xn) {
    float2 A = make_float2(0.5f * (Zk.x + Zn.x), 0.5f * (Zk.y - Zn.y));
    float2 D = make_float2(0.5f * (Zk.x - Zn.x), 0.5f * (Zk.y + Zn.y));
    float2 B = make_float2(D.y, -D.x);
    float2 EB = cmul(E, B);
    *Xk = make_float2(A.x + EB.x, A.y + EB.y);
    *Xn = make_float2(A.x - EB.x, -(A.y - EB.y));
}

__device__ __forceinline__ void spec_pair(float2 Zk, float2 Zn, float2 Kk, float2 Kn,
                                          float2 E, float2* Wk, float2* Wn) {
    float2 Xk, Xn;
    unpack_pair(Zk, Zn, E, &Xk, &Xn);
    float2 Yk = cmul(Xk, Kk);
    float2 Yn = cmul(Xn, Kn);
    float2 Ay = make_float2(0.5f * (Yk.x + Yn.x), 0.5f * (Yk.y - Yn.y));
    float2 Dy = make_float2(0.5f * (Yk.x - Yn.x), 0.5f * (Yk.y + Yn.y));
    float2 By = cmulc(Dy, E);
    *Wk = make_float2(Ay.x - By.y,  Ay.y + By.x);
    *Wn = make_float2(Ay.x + By.y, -Ay.y + By.x);
}

__device__ __forceinline__ float smooth_squash(const float* rk, int i) {
    float ssum = 0.f;
#pragma unroll
    for (int d = -3; d <= 3; d++) {
        int j = i + d;
        j = (j < 0) ? -j : j;
        j = (j > L_SEQ - 1) ? (2 * (L_SEQ - 1) - j) : j;
        ssum += rk[j];
    }
    float v = ssum * (1.0f / 7.0f);
    float a = fabsf(v) - 0.003f;
    return (a > 0.f) ? copysignf(a, v) : 0.f;
}

#define SMEM_K ((2 * KBUF + 7 * TWT8 + TWH_N) * (int)sizeof(float2))
#define SMEM_C ((CB0 + CB1 + 15 * TWT16 + TWH_N) * (int)sizeof(float2))

// ---------------------------------------------------------------------------
// kspec (NT=1024, radix-8) + PDL trigger
// ---------------------------------------------------------------------------
__global__ void __launch_bounds__(NTK, 1) kspec_kernel(const float* __restrict__ kern) {
    extern __shared__ float2 sm2[];
    float2* b0  = sm2;
    float2* b1  = sm2 + KBUF;
    float2* tws = sm2 + 2 * KBUF;
    float2* twh = tws + 7 * TWT8;
    float*  rk  = (float*)b1;

    const int c   = blockIdx.x;
    const int tid = threadIdx.x;
    const float* kr = kern + (size_t)c * L_SEQ;

    for (int i = tid; i < L_SEQ; i += NTK) rk[i] = kr[i];
    {
        float s, cc;
#pragma unroll
        for (int m = 1; m <= 7; m++) {
            sincospif((float)(m * tid) * (1.0f / 4096.0f), &s, &cc);
            tws[((m - 1) << 10) + tid] = make_float2(cc, -s);
        }
#pragma unroll
        for (int k = tid; k < TWH_N; k += NTK) {
            sincospif((float)k * (1.0f / 8192.0f), &s, &cc);
            twh[k] = make_float2(cc, -s);
        }
    }
    __syncthreads();

    {   // fused stage 1 (s=1) from smooth/squash registers -> b0 (M=1)
        float2 v[8];
#pragma unroll
        for (int j = 0; j < 4; j++) {
            const int n = tid + (j << 10);
            v[j] = make_float2(smooth_squash(rk, 2 * n), smooth_squash(rk, 2 * n + 1));
        }
        __syncthreads();
        dft8_half(v);
        const int o = tid << 3;
        b0[SKM(o, 1)] = v[0];
#pragma unroll
        for (int m = 1; m < 8; m++)
            b0[SKM(o + m, 1)] = cmul(tws[((m - 1) << 10) + tid], v[m]);
    }
    __syncthreads();
    stage_r8<0,1,2>(b0, b1, tws, 8, tid);   __syncthreads();
    stage_r8<0,2,1>(b1, b0, tws, 64, tid);  __syncthreads();
    stage_r8<0,1,1>(b0, b1, tws, 512, tid); __syncthreads();
    // P = b1 (M=1); fused r2 finisher + unpack + store (scaled 1/N)
    float2* Kc = g_kspec + (size_t)c * (N_FFT + 1);
    const float inv = 1.0f / (float)N_FFT;
#pragma unroll 1
    for (int u = 0; u < 2; u++) {
        const int q = tid + (u << 10);
        if (q == 0) {
            float2 Pa = b1[SKM(0,1)],    Pb = b1[SKM(4096,1)];
            float2 Pc = b1[SKM(2048,1)], Pd = b1[SKM(6144,1)];
            float2 Z0 = cadd(Pa, Pb), Z4 = csub(Pa, Pb);
            float2 Z2 = cadd(Pc, Pd), Z6 = csub(Pc, Pd);
            Kc[0]     = make_float2((Z0.x + Z0.y) * inv, 0.f);
            Kc[N_FFT] = make_float2((Z0.x - Z0.y) * inv, 0.f);
            Kc[4096]  = make_float2(Z4.x * inv, -Z4.y * inv);
            float2 X2, X6;
            unpack_pair(Z2, Z6, twh[2048], &X2, &X6);
            Kc[2048] = make_float2(X2.x * inv, X2.y * inv);
            Kc[6144] = make_float2(X6.x * inv, X6.y * inv);
        } else {
            const int r = 4096 - q;
            float2 Pa = b1[SKM(q,1)], Pb = b1[SKM(q + 4096,1)];
            float2 Pc = b1[SKM(r,1)], Pd = b1[SKM(r + 4096,1)];
            float2 Zq = cadd(Pa, Pb), Zq4 = csub(Pa, Pb);
            float2 Zr = cadd(Pc, Pd), Znq = csub(Pc, Pd);
            float2 Eq = twh[q];
            float2 Er = make_float2(-Eq.y, -Eq.x);        // E(4096-q)
            float2 Xq, Xnq, Xr, Xpq;
            unpack_pair(Zq, Znq, Eq, &Xq, &Xnq);
            unpack_pair(Zr, Zq4, Er, &Xr, &Xpq);
            Kc[q]         = make_float2(Xq.x * inv,  Xq.y * inv);
            Kc[N_FFT - q] = make_float2(Xnq.x * inv, Xnq.y * inv);
            Kc[r]         = make_float2(Xr.x * inv,  Xr.y * inv);
            Kc[4096 + q]  = make_float2(Xpq.x * inv, Xpq.y * inv);
        }
    }
#if __CUDA_ARCH__ >= 900
    cudaTriggerProgrammaticLaunchCompletion();
#endif
}

// ---------------------------------------------------------------------------
// conv (NT=512, radix-16), PDL secondary
// ---------------------------------------------------------------------------
__global__ void __launch_bounds__(NTC, 1) conv_kernel(const float* __restrict__ x,
                                                      float* __restrict__ out) {
    extern __shared__ float2 sm2[];
    float2* b0  = sm2;
    float2* b1  = sm2 + CB0;
    float2* tws = b1 + CB1;
    float2* twh = tws + 15 * TWT16;

    const int row = blockIdx.x;
    const int c   = row & (NCHAN - 1);
    const int tid = threadIdx.x;
    const float2* xr = (const float2*)(x + (size_t)row * L_SEQ);

    // stage-1 global loads FIRST (latency overlaps the sincospif table fill)
    float2 v1[8];
#pragma unroll
    for (int j = 0; j < 8; j++) v1[j] = xr[tid + (j << 9)];

    {
        float s, cc;
#pragma unroll
        for (int m = 1; m <= 15; m++) {
            sincospif((float)(m * tid) * (1.0f / 4096.0f), &s, &cc);
            tws[((m - 1) << 9) + tid] = make_float2(cc, -s);
        }
#pragma unroll
        for (int k = tid; k < TWH_N; k += NTC) {
            sincospif((float)k * (1.0f / 8192.0f), &s, &cc);
            twh[k] = make_float2(cc, -s);
        }
    }
    __syncthreads();

    {   // fwd stage 1 (s=1, radix-16, upper half zero) -> b0
        float2 v[16];
#pragma unroll
        for (int j = 0; j < 8; j++) v[j] = v1[j];
        dft16_half(v);
        stage1_write16(b0, v, tws, tid);
    }
    __syncthreads();
    stage_r16<0,1,1,16>(b0, b1, tws, tid);  __syncthreads();
    stage_r16<0,1,1,256>(b1, b0, tws, tid); __syncthreads();
    // P = b0

#if __CUDA_ARCH__ >= 900
    cudaGridDependencySynchronize();          // g_kspec ready past this point
#endif

    // fused: fwd r2 finisher + spectral multiply + inv r2 opener -> b1
    const float2* Kc = g_kspec + (size_t)c * (N_FFT + 1);
#pragma unroll 1
    for (int u = 0; u < 4; u++) {
        const int q = tid + (u << 9);
        if (q == 0) {
            float2 Pa = b0[SKM(0,1)],    Pb = b0[SKM(4096,1)];
            float2 Pc = b0[SKM(2048,1)], Pd = b0[SKM(6144,1)];
            float2 Z0 = cadd(Pa, Pb), Z4 = csub(Pa, Pb);
            float2 Z2 = cadd(Pc, Pd), Z6 = csub(Pc, Pd);
            float X0 = Z0.x + Z0.y, XN = Z0.x - Z0.y;
            float2 K0 = Kc[0], KN = Kc[N_FFT];
            float2 Y0 = make_float2(X0 * K0.x, X0 * K0.y);
            float2 YN = make_float2(XN * KN.x, XN * KN.y);
            float2 Ay = make_float2(0.5f * (Y0.x + YN.x), 0.5f * (Y0.y - YN.y));
            float2 Dy = make_float2(0.5f * (Y0.x - YN.x), 0.5f * (Y0.y + YN.y));
            float2 W0 = make_float2(Ay.x - Dy.y, Ay.y + Dy.x);
            float2 W4, Wd;
            spec_pair(Z4, Z4, Kc[4096], Kc[4096], make_float2(0.f, -1.f), &W4, &Wd);
            float2 W2, W6;
            spec_pair(Z2, Z6, Kc[2048], Kc[6144], twh[2048], &W2, &W6);
            b1[SKM(0,1)] = cadd(W0, W4);
            b1[SKM(1,1)] = csub(W0, W4);
            b1[SKM(4096,1)] = cadd(W2, W6);
            float2 t = csub(W2, W6);                 // * winv(2048) = i
            b1[SKM(4097,1)] = make_float2(-t.y, t.x);
        } else {
            const int r = 4096 - q;
            float2 Pa = b0[SKM(q,1)], Pb = b0[SKM(q + 4096,1)];
            float2 Pc = b0[SKM(r,1)], Pd = b0[SKM(r + 4096,1)];
            float2 Zq = cadd(Pa, Pb), Zq4 = csub(Pa, Pb);
            float2 Zr = cadd(Pc, Pd), Znq = csub(Pc, Pd);
            float2 Eq = twh[q];
            float2 Er = make_float2(-Eq.y, -Eq.x);
            float2 Wq, Wnq, Wr, Wpq;
            spec_pair(Zq, Znq, Kc[q], Kc[N_FFT - q], Eq, &Wq, &Wnq);
            spec_pair(Zr, Zq4, Kc[r], Kc[4096 + q], Er, &Wr, &Wpq);
            float2 wq = cmul(Eq, Eq);                 // W^q
            float2 wr = make_float2(-wq.x, wq.y);     // Er^2 = -conj(Eq^2)
            b1[SKM(2 * q, 1)]     = cadd(Wq, Wpq);
            b1[SKM(2 * q + 1, 1)] = cmulc(csub(Wq, Wpq), wq);
            b1[SKM(2 * r, 1)]     = cadd(Wr, Wnq);
            b1[SKM(2 * r + 1, 1)] = cmulc(csub(Wr, Wnq), wr);
        }
    }
    __syncthreads();

    stage_r16<1,1,3,2>(b1, b0, tws, tid);   __syncthreads();  // write M=3: conflict-free
    stage_r16<1,3,1,32>(b0, b1, tws, tid);  __syncthreads();

    {   // final inverse stage s=512 (e=0, twiddle-free): store first half to gmem
        float2 v[16];
#pragma unroll
        for (int j = 0; j < 16; j++) v[j] = b1[SKM(tid + (j << 9), 1)];
        dft16<1>(v);
        float2* outr = (float2*)(out + (size_t)row * L_SEQ);
#pragma unroll
        for (int m = 0; m < 8; m++) outr[tid + (m << 9)] = v[m];
    }
}

// ---------------------------------------------------------------------------
extern "C" void kernel_launch(void* const* d_in, const int* in_sizes, int n_in,
                              void* d_out, int out_size) {
    const float* x;
    const float* kern;
    if (in_sizes[0] == NROWS * L_SEQ) {
        x    = (const float*)d_in[0];
        kern = (const float*)d_in[1];
    } else {
        x    = (const float*)d_in[1];
        kern = (const float*)d_in[0];
    }
    float* out = (float*)d_out;

    cudaFuncSetAttribute(kspec_kernel, cudaFuncAttributeMaxDynamicSharedMemorySize, SMEM_K);
    cudaFuncSetAttribute(conv_kernel,  cudaFuncAttributeMaxDynamicSharedMemorySize, SMEM_C);

    kspec_kernel<<<NCHAN, NTK, SMEM_K>>>(kern);

    cudaLaunchConfig_t cfg = {};
    cfg.gridDim = dim3(NROWS, 1, 1);
    cfg.blockDim = dim3(NTC, 1, 1);
    cfg.dynamicSmemBytes = SMEM_C;
    cfg.stream = 0;
    cudaLaunchAttribute attr[1];
    attr[0].id = cudaLaunchAttributeProgrammaticStreamSerialization;
    attr[0].val.programmaticStreamSerializationAllowed = 1;
    cfg.attrs = attr;
    cfg.numAttrs = 1;
    cudaLaunchKernelEx(&cfg, conv_kernel, x, out);
}

// round 17
// speedup vs baseline: 1.3075x; 1.1704x over previous
#include <cuda_runtime.h>
#include <math.h>

// out[b,c,:] = irfft( rfft(x,16384) * Kspec[c], 16384 )[:8192]
// kspec: radix-8 NT=1024 two-buffer (proven), + PDL trigger.
// conv:  radix-16 NT=512, IN-PLACE single-buffer Stockham (read-all/sync/
//        write-all per stage; whole array lives in CTA registers between),
//        8 twiddle tables (w9..15 derived), __launch_bounds__(512,2) -> occ 2.

#define N_FFT   8192
#define HALF_N  4096
#define NTK     1024
#define NTC     512
#define L_SEQ   8192
#define NCHAN   256
#define NROWS   2048

#define SKM(a,M) ((a) + (M) * ((a) >> 4))
#define KBUF    9216
#define CBUF    9728          // conv single buffer, sized for skew M=3
#define TWT8    1024
#define TWH_N   2052

__device__ float2 g_kspec[(size_t)NCHAN * (N_FFT + 1)];

__device__ __forceinline__ float2 cmul(float2 a, float2 b) {
    return make_float2(a.x * b.x - a.y * b.y, a.x * b.y + a.y * b.x);
}
__device__ __forceinline__ float2 cmulc(float2 a, float2 b) {   // a * conj(b)
    return make_float2(a.x * b.x + a.y * b.y, a.y * b.x - a.x * b.y);
}
__device__ __forceinline__ float2 cadd(float2 a, float2 b) { return make_float2(a.x + b.x, a.y + b.y); }
__device__ __forceinline__ float2 csub(float2 a, float2 b) { return make_float2(a.x - b.x, a.y - b.y); }

template <int INV>
__device__ __forceinline__ void dft8(float2* v) {
    const float u = 0.70710678118654752f;
    float2 apc = cadd(v[0], v[4]), amc = csub(v[0], v[4]);
    float2 bpd = cadd(v[2], v[6]), bmd = csub(v[2], v[6]);
    float2 E0 = cadd(apc, bpd), E2 = csub(apc, bpd), E1, E3;
    if (!INV) { E1 = make_float2(amc.x + bmd.y, amc.y - bmd.x); E3 = make_float2(amc.x - bmd.y, amc.y + bmd.x); }
    else      { E1 = make_float2(amc.x - bmd.y, amc.y + bmd.x); E3 = make_float2(amc.x + bmd.y, amc.y - bmd.x); }
    apc = cadd(v[1], v[5]); amc = csub(v[1], v[5]);
    bpd = cadd(v[3], v[7]); bmd = csub(v[3], v[7]);
    float2 O0 = cadd(apc, bpd), O2 = csub(apc, bpd), O1, O3;
    if (!INV) { O1 = make_float2(amc.x + bmd.y, amc.y - bmd.x); O3 = make_float2(amc.x - bmd.y, amc.y + bmd.x); }
    else      { O1 = make_float2(amc.x - bmd.y, amc.y + bmd.x); O3 = make_float2(amc.x + bmd.y, amc.y - bmd.x); }
    float2 T1, T2, T3;
    if (!INV) {
        T1 = make_float2(u * (O1.x + O1.y), u * (O1.y - O1.x));
        T2 = make_float2(O2.y, -O2.x);
        T3 = make_float2(u * (O3.y - O3.x), -u * (O3.x + O3.y));
    } else {
        T1 = make_float2(u * (O1.x - O1.y), u * (O1.x + O1.y));
        T2 = make_float2(-O2.y, O2.x);
        T3 = make_float2(-u * (O3.x + O3.y), u * (O3.x - O3.y));
    }
    v[0] = cadd(E0, O0); v[4] = csub(E0, O0);
    v[1] = cadd(E1, T1); v[5] = csub(E1, T1);
    v[2] = cadd(E2, T2); v[6] = csub(E2, T2);
    v[3] = cadd(E3, T3); v[7] = csub(E3, T3);
}

__device__ __forceinline__ void dft8_half(float2* v) {
    const float u = 0.70710678118654752f;
    float2 E0 = cadd(v[0], v[2]), E2 = csub(v[0], v[2]);
    float2 E1 = make_float2(v[0].x + v[2].y, v[0].y - v[2].x);
    float2 E3 = make_float2(v[0].x - v[2].y, v[0].y + v[2].x);
    float2 O0 = cadd(v[1], v[3]), O2 = csub(v[1], v[3]);
    float2 O1 = make_float2(v[1].x + v[3].y, v[1].y - v[3].x);
    float2 O3 = make_float2(v[1].x - v[3].y, v[1].y + v[3].x);
    float2 T1 = make_float2(u * (O1.x + O1.y), u * (O1.y - O1.x));
    float2 T2 = make_float2(O2.y, -O2.x);
    float2 T3 = make_float2(u * (O3.y - O3.x), -u * (O3.x + O3.y));
    v[0] = cadd(E0, O0); v[4] = csub(E0, O0);
    v[1] = cadd(E1, T1); v[5] = csub(E1, T1);
    v[2] = cadd(E2, T2); v[6] = csub(E2, T2);
    v[3] = cadd(E3, T3); v[7] = csub(E3, T3);
}

template <int INV>
__device__ __forceinline__ void dft16_combine(float2* v, const float2* e8, const float2* o8) {
    const float c1 = 0.92387953251128674f, s1 = 0.38268343236508977f;
    const float uu = 0.70710678118654752f;
    const float sg = INV ? 1.0f : -1.0f;
    float2 t;
    v[0] = cadd(e8[0], o8[0]);                       v[8]  = csub(e8[0], o8[0]);
    t = cmul(o8[1], make_float2(c1, sg * s1));  v[1] = cadd(e8[1], t); v[9]  = csub(e8[1], t);
    t = cmul(o8[2], make_float2(uu, sg * uu));  v[2] = cadd(e8[2], t); v[10] = csub(e8[2], t);
    t = cmul(o8[3], make_float2(s1, sg * c1));  v[3] = cadd(e8[3], t); v[11] = csub(e8[3], t);
    t = make_float2(-sg * o8[4].y, sg * o8[4].x);
    v[4] = cadd(e8[4], t); v[12] = csub(e8[4], t);
    t = cmul(o8[5], make_float2(-s1, sg * c1)); v[5] = cadd(e8[5], t); v[13] = csub(e8[5], t);
    t = cmul(o8[6], make_float2(-uu, sg * uu)); v[6] = cadd(e8[6], t); v[14] = csub(e8[6], t);
    t = cmul(o8[7], make_float2(-c1, sg * s1)); v[7] = cadd(e8[7], t); v[15] = csub(e8[7], t);
}

template <int INV>
__device__ __forceinline__ void dft16(float2* v) {
    float2 e8[8], o8[8];
#pragma unroll
    for (int j = 0; j < 8; j++) { e8[j] = v[2 * j]; o8[j] = v[2 * j + 1]; }
    dft8<INV>(e8); dft8<INV>(o8);
    dft16_combine<INV>(v, e8, o8);
}

__device__ __forceinline__ void dft16_half(float2* v) {
    float2 e8[8], o8[8];
    e8[0] = v[0]; e8[1] = v[2]; e8[2] = v[4]; e8[3] = v[6];
    o8[0] = v[1]; o8[1] = v[3]; o8[2] = v[5]; o8[3] = v[7];
    dft8_half(e8); dft8_half(o8);
    dft16_combine<0>(v, e8, o8);
}

// radix-8 stage (kspec, NT=1024, two buffers)
template <int INV, int RM, int WM>
__device__ __forceinline__ void stage_r8(const float2* __restrict__ x, float2* __restrict__ y,
                                         const float2* __restrict__ tws, int s, int tid) {
    const int q = tid & (s - 1);
    const int e = tid - q;
    float2 v[8];
#pragma unroll
    for (int j = 0; j < 8; j++) v[j] = x[SKM(tid + (j << 10), RM)];
    dft8<INV>(v);
    const int o = q + (e << 3);
    y[SKM(o, WM)] = v[0];
#pragma unroll
    for (int m = 1; m < 8; m++) {
        float2 w = tws[((m - 1) << 10) + e];
        y[SKM(o + m * s, WM)] = INV ? cmulc(v[m], w) : cmul(w, v[m]);
    }
}

// twiddle fetch for conv: 8 tables, w9..w15 derived from w8
__device__ __forceinline__ float2 get_w(const float2* tw, int e, int m, float2 w8) {
    return (m <= 8) ? tw[((m - 1) << 9) + e] : cmul(w8, tw[((m - 9) << 9) + e]);
}

// conv radix-16 IN-PLACE stage: read-all, sync, write-all, sync
template <int INV, int RM, int WM, int S>
__device__ __forceinline__ void stage_ip16(float2* __restrict__ buf,
                                           const float2* __restrict__ tw, int tid) {
    const int q = tid & (S - 1);
    const int e = tid - q;
    float2 v[16];
#pragma unroll
    for (int j = 0; j < 16; j++) v[j] = buf[SKM(tid + (j << 9), RM)];
    dft16<INV>(v);
    __syncthreads();
    const int o = q + (e << 4);
    buf[SKM(o, WM)] = v[0];
    float2 w8 = tw[(7 << 9) + e];
#pragma unroll
    for (int m = 1; m < 16; m++) {
        float2 w = get_w(tw, e, m, w8);
        buf[SKM(o + m * S, WM)] = INV ? cmulc(v[m], w) : cmul(w, v[m]);
    }
    __syncthreads();
}

// stage-1 (s=1, e=tid) write from registers (buffer previously unused: no pre-sync)
__device__ __forceinline__ void stage1_write16(float2* __restrict__ y, const float2* v,
                                               const float2* __restrict__ tw, int tid) {
    const int o = tid << 4;
    y[SKM(o, 1)] = v[0];
    float2 w8 = tw[(7 << 9) + tid];
#pragma unroll
    for (int m = 1; m < 16; m++) {
        float2 w = get_w(tw, tid, m, w8);
        y[SKM(o + m, 1)] = cmul(w, v[m]);
    }
}

__device__ __forceinline__ void unpack_pair(float2 Zk, float2 Zn, float2 E,
                                            float2* Xk, float2* Xn) {
    float2 A = make_float2(0.5f * (Zk.x + Zn.x), 0.5f * (Zk.y - Zn.y));
    float2 D = make_float2(0.5f * (Zk.x - Zn.x), 0.5f * (Zk.y + Zn.y));
    float2 B = make_float2(D.y, -D.x);
    float2 EB = cmul(E, B);
    *Xk = make_float2(A.x + EB.x, A.y + EB.y);
    *Xn = make_float2(A.x - EB.x, -(A.y - EB.y));
}

__device__ __forceinline__ void spec_pair(float2 Zk, float2 Zn, float2 Kk, float2 Kn,
                                          float2 E, float2* Wk, float2* Wn) {
    float2 Xk, Xn;
    unpack_pair(Zk, Zn, E, &Xk, &Xn);
    float2 Yk = cmul(Xk, Kk);
    float2 Yn = cmul(Xn, Kn);
    float2 Ay = make_float2(0.5f * (Yk.x + Yn.x), 0.5f * (Yk.y - Yn.y));
    float2 Dy = make_float2(0.5f * (Yk.x - Yn.x), 0.5f * (Yk.y + Yn.y));
    float2 By = cmulc(Dy, E);
    *Wk = make_float2(Ay.x - By.y,  Ay.y + By.x);
    *Wn = make_float2(Ay.x + By.y, -Ay.y + By.x);
}

__device__ __forceinline__ float smooth_squash(const float* rk, int i) {
    float ssum = 0.f;
#pragma unroll
    for (int d = -3; d <= 3; d++) {
        int j = i + d;
        j = (j < 0) ? -j : j;
        j = (j > L_SEQ - 1) ? (2 * (L_SEQ - 1) - j) : j;
        ssum += rk[j];
    }
    float v = ssum * (1.0f / 7.0f);
    float a = fabsf(v) - 0.003f;
    return (a > 0.f) ? copysignf(a, v) : 0.f;
}

#define SMEM_K ((2 * KBUF + 7 * TWT8 + TWH_N) * (int)sizeof(float2))
#define SMEM_C ((CBUF + 8 * NTC) * (int)sizeof(float2))    // 108 KB -> 2 CTAs/SM

// ---------------------------------------------------------------------------
// kspec (NT=1024, radix-8, two buffers) + PDL trigger   [unchanged from R16]
// ---------------------------------------------------------------------------
__global__ void __launch_bounds__(NTK, 1) kspec_kernel(const float* __restrict__ kern) {
    extern __shared__ float2 sm2[];
    float2* b0  = sm2;
    float2* b1  = sm2 + KBUF;
    float2* tws = sm2 + 2 * KBUF;
    float2* twh = tws + 7 * TWT8;
    float*  rk  = (float*)b1;

    const int c   = blockIdx.x;
    const int tid = threadIdx.x;
    const float* kr = kern + (size_t)c * L_SEQ;

    for (int i = tid; i < L_SEQ; i += NTK) rk[i] = kr[i];
    {
        float s, cc;
#pragma unroll
        for (int m = 1; m <= 7; m++) {
            sincospif((float)(m * tid) * (1.0f / 4096.0f), &s, &cc);
            tws[((m - 1) << 10) + tid] = make_float2(cc, -s);
        }
#pragma unroll
        for (int k = tid; k < TWH_N; k += NTK) {
            sincospif((float)k * (1.0f / 8192.0f), &s, &cc);
            twh[k] = make_float2(cc, -s);
        }
    }
    __syncthreads();

    {   // fused stage 1 (s=1) from smooth/squash registers -> b0 (M=1)
        float2 v[8];
#pragma unroll
        for (int j = 0; j < 4; j++) {
            const int n = tid + (j << 10);
            v[j] = make_float2(smooth_squash(rk, 2 * n), smooth_squash(rk, 2 * n + 1));
        }
        __syncthreads();
        dft8_half(v);
        const int o = tid << 3;
        b0[SKM(o, 1)] = v[0];
#pragma unroll
        for (int m = 1; m < 8; m++)
            b0[SKM(o + m, 1)] = cmul(tws[((m - 1) << 10) + tid], v[m]);
    }
    __syncthreads();
    stage_r8<0,1,2>(b0, b1, tws, 8, tid);   __syncthreads();
    stage_r8<0,2,1>(b1, b0, tws, 64, tid);  __syncthreads();
    stage_r8<0,1,1>(b0, b1, tws, 512, tid); __syncthreads();
    // P = b1 (M=1); fused r2 finisher + unpack + store (scaled 1/N)
    float2* Kc = g_kspec + (size_t)c * (N_FFT + 1);
    const float inv = 1.0f / (float)N_FFT;
#pragma unroll 1
    for (int u = 0; u < 2; u++) {
        const int q = tid + (u << 10);
        if (q == 0) {
            float2 Pa = b1[SKM(0,1)],    Pb = b1[SKM(4096,1)];
            float2 Pc = b1[SKM(2048,1)], Pd = b1[SKM(6144,1)];
            float2 Z0 = cadd(Pa, Pb), Z4 = csub(Pa, Pb);
            float2 Z2 = cadd(Pc, Pd), Z6 = csub(Pc, Pd);
            Kc[0]     = make_float2((Z0.x + Z0.y) * inv, 0.f);
            Kc[N_FFT] = make_float2((Z0.x - Z0.y) * inv, 0.f);
            Kc[4096]  = make_float2(Z4.x * inv, -Z4.y * inv);
            float2 X2, X6;
            unpack_pair(Z2, Z6, twh[2048], &X2, &X6);
            Kc[2048] = make_float2(X2.x * inv, X2.y * inv);
            Kc[6144] = make_float2(X6.x * inv, X6.y * inv);
        } else {
            const int r = 4096 - q;
            float2 Pa = b1[SKM(q,1)], Pb = b1[SKM(q + 4096,1)];
            float2 Pc = b1[SKM(r,1)], Pd = b1[SKM(r + 4096,1)];
            float2 Zq = cadd(Pa, Pb), Zq4 = csub(Pa, Pb);
            float2 Zr = cadd(Pc, Pd), Znq = csub(Pc, Pd);
            float2 Eq = twh[q];
            float2 Er = make_float2(-Eq.y, -Eq.x);        // E(4096-q)
            float2 Xq, Xnq, Xr, Xpq;
            unpack_pair(Zq, Znq, Eq, &Xq, &Xnq);
            unpack_pair(Zr, Zq4, Er, &Xr, &Xpq);
            Kc[q]         = make_float2(Xq.x * inv,  Xq.y * inv);
            Kc[N_FFT - q] = make_float2(Xnq.x * inv, Xnq.y * inv);
            Kc[r]         = make_float2(Xr.x * inv,  Xr.y * inv);
            Kc[4096 + q]  = make_float2(Xpq.x * inv, Xpq.y * inv);
        }
    }
#if __CUDA_ARCH__ >= 900
    cudaTriggerProgrammaticLaunchCompletion();
#endif
}

// ---------------------------------------------------------------------------
// conv (NT=512, radix-16, in-place single buffer, occ 2), PDL secondary
// ---------------------------------------------------------------------------
__global__ void __launch_bounds__(NTC, 2) conv_kernel(const float* __restrict__ x,
                                                      float* __restrict__ out) {
    extern __shared__ float2 sm2[];
    float2* buf = sm2;
    float2* tw  = sm2 + CBUF;          // 8 tables of 512: w^(m*e), m=1..8

    const int row = blockIdx.x;
    const int c   = row & (NCHAN - 1);
    const int tid = threadIdx.x;
    const float2* xr = (const float2*)(x + (size_t)row * L_SEQ);

    // stage-1 global loads FIRST (latency overlaps the table fill)
    float2 v1[8];
#pragma unroll
    for (int j = 0; j < 8; j++) v1[j] = xr[tid + (j << 9)];

    {   // fill 8 twiddle tables: tw[(m-1)*512+e] = e^{-2 pi i m e/8192}
        float s, cc;
#pragma unroll
        for (int m = 1; m <= 8; m++) {
            sincospif((float)(m * tid) * (1.0f / 4096.0f), &s, &cc);
            tw[((m - 1) << 9) + tid] = make_float2(cc, -s);
        }
    }
    __syncthreads();

    {   // fwd stage 1 (s=1, radix-16, upper half zero) -> buf (M=1)
        float2 v[16];
#pragma unroll
        for (int j = 0; j < 8; j++) v[j] = v1[j];
        dft16_half(v);
        stage1_write16(buf, v, tw, tid);
    }
    __syncthreads();
    stage_ip16<0,1,1,16>(buf, tw, tid);
    stage_ip16<0,1,1,256>(buf, tw, tid);
    // P = buf (natural order, M=1)

#if __CUDA_ARCH__ >= 900
    cudaGridDependencySynchronize();          // g_kspec ready past this point
#endif

    // fused seam: fwd r2 finisher + spectral multiply + inv r2 opener, IN PLACE
    const float2* Kc = g_kspec + (size_t)c * (N_FFT + 1);
    {
        float2 P[16];
#pragma unroll
        for (int u = 0; u < 4; u++) {
            const int q = tid + (u << 9);
            const int r = (q == 0) ? 2048 : 4096 - q;
            P[4*u+0] = buf[SKM(q, 1)];
            P[4*u+1] = buf[SKM(q + 4096, 1)];
            P[4*u+2] = buf[SKM(r, 1)];
            P[4*u+3] = buf[SKM(r + 4096, 1)];
        }
        __syncthreads();
#pragma unroll
        for (int u = 0; u < 4; u++) {
            const int q = tid + (u << 9);
            float2 Pa = P[4*u+0], Pb = P[4*u+1], Pc = P[4*u+2], Pd = P[4*u+3];
            if (q == 0) {
                float2 Z0 = cadd(Pa, Pb), Z4 = csub(Pa, Pb);
                float2 Z2 = cadd(Pc, Pd), Z6 = csub(Pc, Pd);
                float X0 = Z0.x + Z0.y, XN = Z0.x - Z0.y;
                float2 K0 = Kc[0], KN = Kc[N_FFT];
                float2 Y0 = make_float2(X0 * K0.x, X0 * K0.y);
                float2 YN = make_float2(XN * KN.x, XN * KN.y);
                float2 Ay = make_float2(0.5f * (Y0.x + YN.x), 0.5f * (Y0.y - YN.y));
                float2 Dy = make_float2(0.5f * (Y0.x - YN.x), 0.5f * (Y0.y + YN.y));
                float2 W0 = make_float2(Ay.x - Dy.y, Ay.y + Dy.x);
                float2 W4, Wd;
                spec_pair(Z4, Z4, Kc[4096], Kc[4096], make_float2(0.f, -1.f), &W4, &Wd);
                float2 W2, W6;
                const float2 E2048 = make_float2(0.70710678118654752f, -0.70710678118654752f);
                spec_pair(Z2, Z6, Kc[2048], Kc[6144], E2048, &W2, &W6);
                buf[SKM(0,1)] = cadd(W0, W4);
                buf[SKM(1,1)] = csub(W0, W4);
                buf[SKM(4096,1)] = cadd(W2, W6);
                float2 t = csub(W2, W6);                 // * winv(2048) = i
                buf[SKM(4097,1)] = make_float2(-t.y, t.x);
            } else {
                const int r = 4096 - q;
                float2 Zq = cadd(Pa, Pb), Zq4 = csub(Pa, Pb);
                float2 Zr = cadd(Pc, Pd), Znq = csub(Pc, Pd);
                float s, cc;
                sincospif((float)q * (1.0f / 8192.0f), &s, &cc);
                float2 Eq = make_float2(cc, -s);
                float2 Er = make_float2(-Eq.y, -Eq.x);
                float2 Wq, Wnq, Wr, Wpq;
                spec_pair(Zq, Znq, Kc[q], Kc[N_FFT - q], Eq, &Wq, &Wnq);
                spec_pair(Zr, Zq4, Kc[r], Kc[4096 + q], Er, &Wr, &Wpq);
                float2 wq = cmul(Eq, Eq);                 // W^q
                float2 wr = make_float2(-wq.x, wq.y);     // Er^2 = -conj(Eq^2)
                buf[SKM(2 * q, 1)]     = cadd(Wq, Wpq);
                buf[SKM(2 * q + 1, 1)] = cmulc(csub(Wq, Wpq), wq);
                buf[SKM(2 * r, 1)]     = cadd(Wr, Wnq);
                buf[SKM(2 * r + 1, 1)] = cmulc(csub(Wr, Wnq), wr);
            }
        }
        __syncthreads();
    }

    stage_ip16<1,1,3,2>(buf, tw, tid);    // write M=3 (conflict-free)
    stage_ip16<1,3,1,32>(buf, tw, tid);   // read M=3, write M=1

    {   // final inverse stage s=512 (e=0, twiddle-free): store first half to gmem
        float2 v[16];
#pragma unroll
        for (int j = 0; j < 16; j++) v[j] = buf[SKM(tid + (j << 9), 1)];
        dft16<1>(v);
        float2* outr = (float2*)(out + (size_t)row * L_SEQ);
#pragma unroll
        for (int m = 0; m < 8; m++) outr[tid + (m << 9)] = v[m];
    }
}

// ---------------------------------------------------------------------------
extern "C" void kernel_launch(void* const* d_in, const int* in_sizes, int n_in,
                              void* d_out, int out_size) {
    const float* x;
    const float* kern;
    if (in_sizes[0] == NROWS * L_SEQ) {
        x    = (const float*)d_in[0];
        kern = (const float*)d_in[1];
    } else {
        x    = (const float*)d_in[1];
        kern = (const float*)d_in[0];
    }
    float* out = (float*)d_out;

    cudaFuncSetAttribute(kspec_kernel, cudaFuncAttributeMaxDynamicSharedMemorySize, SMEM_K);
    cudaFuncSetAttribute(conv_kernel,  cudaFuncAttributeMaxDynamicSharedMemorySize, SMEM_C);

    kspec_kernel<<<NCHAN, NTK, SMEM_K>>>(kern);

    cudaLaunchConfig_t cfg = {};
    cfg.gridDim = dim3(NROWS, 1, 1);
    cfg.blockDim = dim3(NTC, 1, 1);
    cfg.dynamicSmemBytes = SMEM_C;
    cfg.stream = 0;
    cudaLaunchAttribute attr[1];
    attr[0].id = cudaLaunchAttributeProgrammaticStreamSerialization;
    attr[0].val.programmaticStreamSerializationAllowed = 1;
    cfg.attrs = attr;
    cfg.numAttrs = 1;
    cudaLaunchKernelEx(&cfg, conv_kernel, x, out);
}